// round 1
// baseline (speedup 1.0000x reference)
#include <cuda_runtime.h>
#include <math.h>

// Problem constants (baked, match reference)
#define BSZ    2048
#define LATENT 128
#define NCLS   8
#define HID    1024
#define DFEAT  512
#define NMAX   4096
#define PADMAX 2560   // 2048 + 7*63 rounded up; per-class segments 64-aligned

__constant__ int d_counts[8] = {1024,1536,2048,2560,3072,3584,3840,4096};

// Scratch (static device globals — no allocation in kernel_launch)
__device__ float g_h[BSZ * HID];          //  8 MB  MLP hidden
__device__ float g_Tc[PADMAX * HID];      // 10 MB  t, compacted by class
__device__ float g_logits[PADMAX * NMAX]; // 42 MB  logits -> unnormalized alpha
__device__ float g_inv[PADMAX];           // 1/sum(exp) per compacted row
__device__ int   g_perm[PADMAX];          // compacted pos -> original row
__device__ int   g_pos[BSZ];              // original row -> compacted pos
__device__ int   g_off[9];                // 64-aligned class segment starts
__device__ int   g_end[8];                // real (unpadded) segment ends

__device__ __forceinline__ float gelu_exact(float v) {
    return 0.5f * v * (1.0f + erff(v * 0.70710678118654752f));
}

// ---------------------------------------------------------------------------
// Group rows by class: counts -> 64-aligned offsets -> scatter perm/pos
// ---------------------------------------------------------------------------
__global__ void group_kernel(const int* __restrict__ cid) {
    __shared__ int s_cnt[8];
    __shared__ int s_off[8];
    __shared__ int s_cur[8];
    int t = threadIdx.x;
    if (t < 8) { s_cnt[t] = 0; s_cur[t] = 0; }
    __syncthreads();
    for (int m = t; m < BSZ; m += blockDim.x) atomicAdd(&s_cnt[cid[m]], 1);
    __syncthreads();
    if (t == 0) {
        int o = 0;
        for (int c = 0; c < 8; c++) {
            s_off[c] = o;
            g_off[c] = o;
            g_end[c] = o + s_cnt[c];
            o = (o + s_cnt[c] + 63) & ~63;   // 64-align next class
        }
        g_off[8] = o;
    }
    __syncthreads();
    for (int m = t; m < BSZ; m += blockDim.x) {
        int c = cid[m];
        int p = s_off[c] + atomicAdd(&s_cur[c], 1);
        g_perm[p] = m;
        g_pos[m]  = p;
    }
}

// ---------------------------------------------------------------------------
// MLP1: h = gelu(z @ W1[:128] + b1 + W1[128+cid])    [2048 x 1024]
// 64x64x16 tiles, 256 threads, 4x4 micro-tile
// ---------------------------------------------------------------------------
__global__ __launch_bounds__(256)
void mlp1_kernel(const float* __restrict__ z, const int* __restrict__ cid,
                 const float* __restrict__ W1, const float* __restrict__ b1) {
    __shared__ float As[16][64];
    __shared__ float Bs[16][64];
    const int tid = threadIdx.x;
    const int tx = tid & 15, ty = tid >> 4;
    const int m0 = blockIdx.y * 64, n0 = blockIdx.x * 64;
    const int ar = tid >> 2, ak = (tid & 3) * 4;
    const int br = tid >> 4, bc = (tid & 15) * 4;
    float acc[4][4] = {};

    for (int k0 = 0; k0 < LATENT; k0 += 16) {
        float4 av = *(const float4*)&z[(size_t)(m0 + ar) * LATENT + k0 + ak];
        As[ak+0][ar] = av.x; As[ak+1][ar] = av.y;
        As[ak+2][ar] = av.z; As[ak+3][ar] = av.w;
        *(float4*)&Bs[br][bc] = *(const float4*)&W1[(size_t)(k0 + br) * HID + n0 + bc];
        __syncthreads();
        #pragma unroll
        for (int k = 0; k < 16; k++) {
            float4 a4 = *(const float4*)&As[k][ty * 4];
            float4 b4 = *(const float4*)&Bs[k][tx * 4];
            float a_[4] = {a4.x, a4.y, a4.z, a4.w};
            float b_[4] = {b4.x, b4.y, b4.z, b4.w};
            #pragma unroll
            for (int i = 0; i < 4; i++)
                #pragma unroll
                for (int j = 0; j < 4; j++)
                    acc[i][j] += a_[i] * b_[j];
        }
        __syncthreads();
    }

    #pragma unroll
    for (int i = 0; i < 4; i++) {
        int m = m0 + ty * 4 + i;
        size_t crow = (size_t)(LATENT + cid[m]) * HID;
        #pragma unroll
        for (int j = 0; j < 4; j++) {
            int n = n0 + tx * 4 + j;
            float v = acc[i][j] + b1[n] + W1[crow + n];
            g_h[(size_t)m * HID + n] = gelu_exact(v);
        }
    }
}

// ---------------------------------------------------------------------------
// MLP2: t = gelu(h @ W2 + b2), scattered to class-compacted layout g_Tc
// ---------------------------------------------------------------------------
__global__ __launch_bounds__(256)
void mlp2_kernel(const float* __restrict__ W2, const float* __restrict__ b2) {
    __shared__ float As[16][64];
    __shared__ float Bs[16][64];
    const int tid = threadIdx.x;
    const int tx = tid & 15, ty = tid >> 4;
    const int m0 = blockIdx.y * 64, n0 = blockIdx.x * 64;
    const int ar = tid >> 2, ak = (tid & 3) * 4;
    const int br = tid >> 4, bc = (tid & 15) * 4;
    float acc[4][4] = {};

    for (int k0 = 0; k0 < HID; k0 += 16) {
        float4 av = *(const float4*)&g_h[(size_t)(m0 + ar) * HID + k0 + ak];
        As[ak+0][ar] = av.x; As[ak+1][ar] = av.y;
        As[ak+2][ar] = av.z; As[ak+3][ar] = av.w;
        *(float4*)&Bs[br][bc] = *(const float4*)&W2[(size_t)(k0 + br) * HID + n0 + bc];
        __syncthreads();
        #pragma unroll
        for (int k = 0; k < 16; k++) {
            float4 a4 = *(const float4*)&As[k][ty * 4];
            float4 b4 = *(const float4*)&Bs[k][tx * 4];
            float a_[4] = {a4.x, a4.y, a4.z, a4.w};
            float b_[4] = {b4.x, b4.y, b4.z, b4.w};
            #pragma unroll
            for (int i = 0; i < 4; i++)
                #pragma unroll
                for (int j = 0; j < 4; j++)
                    acc[i][j] += a_[i] * b_[j];
        }
        __syncthreads();
    }

    #pragma unroll
    for (int i = 0; i < 4; i++) {
        int m = m0 + ty * 4 + i;
        int p = g_pos[m];
        #pragma unroll
        for (int j = 0; j < 4; j++) {
            int n = n0 + tx * 4 + j;
            g_Tc[(size_t)p * HID + n] = gelu_exact(acc[i][j] + b2[n]);
        }
    }
}

// ---------------------------------------------------------------------------
// logits = Tc @ Wa[c] + ba[c]  (grouped GEMM over 64-aligned class segments)
// All COUNTS are multiples of 64, so N has no ragged tiles.
// ---------------------------------------------------------------------------
__global__ __launch_bounds__(256)
void logits_kernel(const float* __restrict__ Wa, const float* __restrict__ ba) {
    const int p0 = blockIdx.y * 64;
    if (p0 >= g_off[8]) return;
    int c = 0;
    #pragma unroll
    for (int i = 0; i < 8; i++) if (g_off[i + 1] <= p0) c = i + 1;
    const int Nc = d_counts[c];
    const int n0 = blockIdx.x * 64;
    if (n0 >= Nc) return;
    const int endc = g_end[c];

    __shared__ float As[16][64];
    __shared__ float Bs[16][64];
    const int tid = threadIdx.x;
    const int tx = tid & 15, ty = tid >> 4;
    const int ar = tid >> 2, ak = (tid & 3) * 4;
    const int br = tid >> 4, bc = (tid & 15) * 4;
    const bool avalid = (p0 + ar) < endc;       // padding rows read as zero
    const float* Bmat = Wa + (size_t)c * HID * NMAX;
    float acc[4][4] = {};

    for (int k0 = 0; k0 < HID; k0 += 16) {
        float4 av = avalid ? *(const float4*)&g_Tc[(size_t)(p0 + ar) * HID + k0 + ak]
                           : make_float4(0.f, 0.f, 0.f, 0.f);
        As[ak+0][ar] = av.x; As[ak+1][ar] = av.y;
        As[ak+2][ar] = av.z; As[ak+3][ar] = av.w;
        *(float4*)&Bs[br][bc] = *(const float4*)&Bmat[(size_t)(k0 + br) * NMAX + n0 + bc];
        __syncthreads();
        #pragma unroll
        for (int k = 0; k < 16; k++) {
            float4 a4 = *(const float4*)&As[k][ty * 4];
            float4 b4 = *(const float4*)&Bs[k][tx * 4];
            float a_[4] = {a4.x, a4.y, a4.z, a4.w};
            float b_[4] = {b4.x, b4.y, b4.z, b4.w};
            #pragma unroll
            for (int i = 0; i < 4; i++)
                #pragma unroll
                for (int j = 0; j < 4; j++)
                    acc[i][j] += a_[i] * b_[j];
        }
        __syncthreads();
    }

    const float* brow = ba + (size_t)c * NMAX;
    #pragma unroll
    for (int i = 0; i < 4; i++) {
        int p = p0 + ty * 4 + i;
        #pragma unroll
        for (int j = 0; j < 4; j++) {
            int n = n0 + tx * 4 + j;
            g_logits[(size_t)p * NMAX + n] = acc[i][j] + brow[n];
        }
    }
}

// ---------------------------------------------------------------------------
// Softmax over valid n; stores exp(x - max) in place, 1/sum in g_inv
// ---------------------------------------------------------------------------
__global__ __launch_bounds__(256)
void softmax_kernel() {
    const int p = blockIdx.x;
    if (p >= g_off[8]) return;
    int c = 0;
    #pragma unroll
    for (int i = 0; i < 8; i++) if (g_off[i + 1] <= p) c = i + 1;
    if (p >= g_end[c]) return;
    const int Nc = d_counts[c];
    float* row = g_logits + (size_t)p * NMAX;

    __shared__ float sm[8], ss[8];
    const int tid = threadIdx.x;

    float mx = -1e30f;
    for (int n = tid; n < Nc; n += 256) mx = fmaxf(mx, row[n]);
    #pragma unroll
    for (int o = 16; o; o >>= 1) mx = fmaxf(mx, __shfl_xor_sync(0xffffffffu, mx, o));
    if ((tid & 31) == 0) sm[tid >> 5] = mx;
    __syncthreads();
    mx = sm[0];
    #pragma unroll
    for (int w = 1; w < 8; w++) mx = fmaxf(mx, sm[w]);

    float s = 0.f;
    for (int n = tid; n < Nc; n += 256) {
        float e = expf(row[n] - mx);
        row[n] = e;
        s += e;
    }
    #pragma unroll
    for (int o = 16; o; o >>= 1) s += __shfl_xor_sync(0xffffffffu, s, o);
    if ((tid & 31) == 0) ss[tid >> 5] = s;
    __syncthreads();
    if (tid == 0) {
        float tot = 0.f;
        #pragma unroll
        for (int w = 0; w < 8; w++) tot += ss[w];
        g_inv[p] = 1.0f / tot;
    }
}

// ---------------------------------------------------------------------------
// out[perm[p]] = (alpha[p] @ Xbuf[c]) * g_inv[p]   (normalization fused)
// ---------------------------------------------------------------------------
__global__ __launch_bounds__(256)
void out_kernel(const float* __restrict__ Xbuf, float* __restrict__ out) {
    const int p0 = blockIdx.y * 64;
    if (p0 >= g_off[8]) return;
    int c = 0;
    #pragma unroll
    for (int i = 0; i < 8; i++) if (g_off[i + 1] <= p0) c = i + 1;
    const int Nc = d_counts[c];
    const int endc = g_end[c];
    const int n0 = blockIdx.x * 64;

    __shared__ float As[16][64];
    __shared__ float Bs[16][64];
    const int tid = threadIdx.x;
    const int tx = tid & 15, ty = tid >> 4;
    const int ar = tid >> 2, ak = (tid & 3) * 4;
    const int br = tid >> 4, bc = (tid & 15) * 4;
    const bool avalid = (p0 + ar) < endc;
    const float* Bmat = Xbuf + (size_t)c * NMAX * DFEAT;
    float acc[4][4] = {};

    for (int k0 = 0; k0 < Nc; k0 += 16) {
        float4 av = avalid ? *(const float4*)&g_logits[(size_t)(p0 + ar) * NMAX + k0 + ak]
                           : make_float4(0.f, 0.f, 0.f, 0.f);
        As[ak+0][ar] = av.x; As[ak+1][ar] = av.y;
        As[ak+2][ar] = av.z; As[ak+3][ar] = av.w;
        *(float4*)&Bs[br][bc] = *(const float4*)&Bmat[(size_t)(k0 + br) * DFEAT + n0 + bc];
        __syncthreads();
        #pragma unroll
        for (int k = 0; k < 16; k++) {
            float4 a4 = *(const float4*)&As[k][ty * 4];
            float4 b4 = *(const float4*)&Bs[k][tx * 4];
            float a_[4] = {a4.x, a4.y, a4.z, a4.w};
            float b_[4] = {b4.x, b4.y, b4.z, b4.w};
            #pragma unroll
            for (int i = 0; i < 4; i++)
                #pragma unroll
                for (int j = 0; j < 4; j++)
                    acc[i][j] += a_[i] * b_[j];
        }
        __syncthreads();
    }

    #pragma unroll
    for (int i = 0; i < 4; i++) {
        int p = p0 + ty * 4 + i;
        if (p < endc) {
            int m = g_perm[p];
            float inv = g_inv[p];
            #pragma unroll
            for (int j = 0; j < 4; j++) {
                int n = n0 + tx * 4 + j;
                out[(size_t)m * DFEAT + n] = acc[i][j] * inv;
            }
        }
    }
}

// ---------------------------------------------------------------------------
extern "C" void kernel_launch(void* const* d_in, const int* in_sizes, int n_in,
                              void* d_out, int out_size) {
    const float* z   = (const float*)d_in[0];
    const int*   cid = (const int*)  d_in[1];
    const float* W1  = (const float*)d_in[2];
    const float* b1  = (const float*)d_in[3];
    const float* W2  = (const float*)d_in[4];
    const float* b2  = (const float*)d_in[5];
    const float* Wa  = (const float*)d_in[6];
    const float* ba  = (const float*)d_in[7];
    const float* Xb  = (const float*)d_in[8];
    float* out = (float*)d_out;

    group_kernel<<<1, 1024>>>(cid);
    mlp1_kernel<<<dim3(HID / 64, BSZ / 64), 256>>>(z, cid, W1, b1);
    mlp2_kernel<<<dim3(HID / 64, BSZ / 64), 256>>>(W2, b2);
    logits_kernel<<<dim3(NMAX / 64, PADMAX / 64), 256>>>(Wa, ba);
    softmax_kernel<<<PADMAX, 256>>>();
    out_kernel<<<dim3(DFEAT / 64, PADMAX / 64), 256>>>(Xb, out);
}